// round 1
// baseline (speedup 1.0000x reference)
#include <cuda_runtime.h>
#include <cstdint>
#include <cstddef>

#define BATCH 32
#define SEQT  2048
#define INSZ  512
#define HID   512
#define G3    1536
#define NB    128        // persistent CTAs for the scan (<= 148 SMs -> co-resident)
#define NT    256

// ---- device scratch (static allocs are the sanctioned no-cudaMalloc path) ----
__device__ float g_xg[(size_t)SEQT * BATCH * G3];   // [t][b][3H], ~402 MB BSS
__device__ float g_h[2][BATCH * HID];               // double-buffered hidden state
__device__ unsigned g_bar_count;                    // grid barrier (ends at 0 each launch)
__device__ unsigned g_bar_gen;                      // monotonic generation

// =============================================================
// Kernel A: x_gates = input @ W_ih^T + b_ih   (fp32 SGEMM 128x128x8)
// =============================================================
__global__ __launch_bounds__(256) void gemm_xgates(
    const float* __restrict__ A,      // [B*T, 512] row-major (b major, t minor)
    const float* __restrict__ Wih,    // [1536, 512]
    const float* __restrict__ bih) {  // [1536]
  __shared__ float As[8][128];
  __shared__ float Bs[8][128];
  const int tid = threadIdx.x;
  const int m0 = blockIdx.y << 7;
  const int n0 = blockIdx.x << 7;
  const int tx = tid & 15, ty = tid >> 4;
  const int lr = tid >> 1;
  const int lc = (tid & 1) << 2;

  float acc[8][8];
#pragma unroll
  for (int i = 0; i < 8; i++)
#pragma unroll
    for (int j = 0; j < 8; j++) acc[i][j] = 0.f;

  const float* Ap = A + (size_t)(m0 + lr) * INSZ + lc;
  const float* Bp = Wih + (size_t)(n0 + lr) * INSZ + lc;

  for (int k0 = 0; k0 < INSZ; k0 += 8) {
    float4 av = *(const float4*)(Ap + k0);
    float4 bv = *(const float4*)(Bp + k0);
    As[lc + 0][lr] = av.x; As[lc + 1][lr] = av.y;
    As[lc + 2][lr] = av.z; As[lc + 3][lr] = av.w;
    Bs[lc + 0][lr] = bv.x; Bs[lc + 1][lr] = bv.y;
    Bs[lc + 2][lr] = bv.z; Bs[lc + 3][lr] = bv.w;
    __syncthreads();
#pragma unroll
    for (int k = 0; k < 8; k++) {
      float af[8], bf[8];
      *(float4*)(af)     = *(const float4*)&As[k][ty * 8];
      *(float4*)(af + 4) = *(const float4*)&As[k][ty * 8 + 4];
      *(float4*)(bf)     = *(const float4*)&Bs[k][tx * 8];
      *(float4*)(bf + 4) = *(const float4*)&Bs[k][tx * 8 + 4];
#pragma unroll
      for (int i = 0; i < 8; i++)
#pragma unroll
        for (int j = 0; j < 8; j++) acc[i][j] += af[i] * bf[j];
    }
    __syncthreads();
  }

  float bb_[8];
  *(float4*)(bb_)     = *(const float4*)(bih + n0 + tx * 8);
  *(float4*)(bb_ + 4) = *(const float4*)(bih + n0 + tx * 8 + 4);
#pragma unroll
  for (int i = 0; i < 8; i++) {
    int m = m0 + ty * 8 + i;
    int b = m >> 11;        // / 2048
    int t = m & 2047;       // % 2048
    float* orow = g_xg + ((size_t)t * BATCH + b) * G3 + n0 + tx * 8;
    float4 o0, o1;
    o0.x = acc[i][0] + bb_[0]; o0.y = acc[i][1] + bb_[1];
    o0.z = acc[i][2] + bb_[2]; o0.w = acc[i][3] + bb_[3];
    o1.x = acc[i][4] + bb_[4]; o1.y = acc[i][5] + bb_[5];
    o1.z = acc[i][6] + bb_[6]; o1.w = acc[i][7] + bb_[7];
    *(float4*)(orow)     = o0;
    *(float4*)(orow + 4) = o1;
  }
}

// =============================================================
// Kernel B: persistent GRU scan with software grid barrier
// =============================================================
__device__ __forceinline__ void grid_barrier() {
  __syncthreads();
  if (threadIdx.x == 0) {
    __threadfence();  // release all prior global writes
    unsigned gen = *(volatile unsigned*)&g_bar_gen;  // read BEFORE arriving
    unsigned a = atomicAdd(&g_bar_count, 1u);
    if (a == (unsigned)(gridDim.x - 1)) {
      g_bar_count = 0;               // sole writer at this point
      __threadfence();
      atomicAdd(&g_bar_gen, 1u);     // release next phase
    } else {
      while (*(volatile unsigned*)&g_bar_gen == gen) { }
    }
    __threadfence();  // acquire
  }
  __syncthreads();
}

__device__ __forceinline__ float sigmoid_f(float x) {
  return 1.f / (1.f + __expf(-x));
}
__device__ __forceinline__ float tanh_f(float x) {
  float e = __expf(-2.f * x);
  return (1.f - e) / (1.f + e);
}

// dynamic shared layout (floats):
//   ws  [12 * 512]   = 6144    W_hh slice, row r = jj*3 + g  -> global row g*512 + j0 + jj
//   hs  [32 * 512]   = 16384   staged previous h
//   red [8 * 48]     = 384     per-warp reduced dot products
//   bh  [16]                   bias_hh slice
#define SMEM_FLOATS (6144 + 16384 + 384 + 16)

__global__ __launch_bounds__(NT, 1) void gru_scan(
    const float* __restrict__ Whh,   // [1536, 512]
    const float* __restrict__ bhh,   // [1536]
    const float* __restrict__ h0,    // [1, 32, 512]
    float* __restrict__ out) {       // [32, 2048, 512]
  extern __shared__ float smem[];
  float* ws  = smem;
  float* hs  = smem + 6144;
  float* red = hs + 16384;
  float* bh  = red + 384;

  const int tid  = threadIdx.x;
  const int j0   = blockIdx.x << 2;           // 4 hidden units per CTA
  const int w    = tid >> 5;
  const int lane = tid & 31;
  const int bg   = w >> 1;                    // batch group (8 batches)
  const int rg   = w & 1;                     // row group (6 of 12 rows)
  const int b0   = bg << 3;

  // --- load W_hh slice into shared (row-major [12][512]) ---
  for (int idx = tid; idx < 12 * (INSZ / 4); idx += NT) {
    int r  = idx >> 7;          // 0..11
    int kc = idx & 127;
    int jj = r / 3;
    int g  = r - jj * 3;
    float4 v = *(const float4*)(Whh + (size_t)(g * HID + j0 + jj) * HID + (kc << 2));
    *(float4*)&ws[r * INSZ + (kc << 2)] = v;
  }
  if (tid < 12) {
    int jj = tid / 3, g = tid - jj * 3;
    bh[tid] = bhh[g * HID + j0 + jj];
  }
  // --- copy h0 slice into g_h[0] ---
  for (int idx = tid; idx < BATCH * 4; idx += NT) {
    int b = idx >> 2, jj = idx & 3;
    g_h[0][b * HID + j0 + jj] = h0[b * HID + j0 + jj];
  }
  grid_barrier();  // full h0 visible everywhere

  const float* wsr = ws + (rg * 6) * INSZ;

  for (int t = 0; t < SEQT; t++) {
    const float* hp = g_h[t & 1];
    float* hn = g_h[(t + 1) & 1];

    // --- stage previous h (64 KB) into shared, bypassing stale L1 ---
    {
      const float4* hp4 = (const float4*)hp;
      float4* hs4 = (float4*)hs;
#pragma unroll
      for (int i = 0; i < 16; i++) {
        int idx = i * NT + tid;   // 4096 float4 total
        hs4[idx] = __ldcg(hp4 + idx);
      }
    }
    __syncthreads();

    // --- per-warp 8b x 6r register tile, k split across 32 lanes ---
    float acc[48];
#pragma unroll
    for (int c = 0; c < 48; c++) acc[c] = 0.f;

    const float* hsb = hs + b0 * HID;
#pragma unroll
    for (int i4 = 0; i4 < 4; i4++) {
      int k = i4 * 128 + (lane << 2);
      float4 wv[6], hv[8];
#pragma unroll
      for (int rr = 0; rr < 6; rr++)
        wv[rr] = *(const float4*)(wsr + rr * INSZ + k);
#pragma unroll
      for (int bb = 0; bb < 8; bb++)
        hv[bb] = *(const float4*)(hsb + bb * HID + k);
#pragma unroll
      for (int rr = 0; rr < 6; rr++)
#pragma unroll
        for (int bb = 0; bb < 8; bb++) {
          float s = acc[rr * 8 + bb];
          s += wv[rr].x * hv[bb].x;
          s += wv[rr].y * hv[bb].y;
          s += wv[rr].z * hv[bb].z;
          s += wv[rr].w * hv[bb].w;
          acc[rr * 8 + bb] = s;
        }
    }

    // --- butterfly reduce over lanes; scatter 48 sums to shared ---
#pragma unroll
    for (int rr = 0; rr < 6; rr++)
#pragma unroll
      for (int bb = 0; bb < 8; bb++) {
        float v = acc[rr * 8 + bb];
        v += __shfl_xor_sync(0xffffffffu, v, 16);
        v += __shfl_xor_sync(0xffffffffu, v, 8);
        v += __shfl_xor_sync(0xffffffffu, v, 4);
        v += __shfl_xor_sync(0xffffffffu, v, 2);
        v += __shfl_xor_sync(0xffffffffu, v, 1);
        const int c = rr * 8 + bb;
        if (lane == (c & 31)) red[w * 48 + c] = v;
      }
    __syncwarp();

    // --- gate math + state update: 16 lanes/warp, one (b, j) each ---
    if (lane < 16) {
      int bb  = lane >> 1;
      int jj2 = lane & 1;
      int b   = b0 + bb;
      int j   = j0 + (rg << 1) + jj2;
      float sr = red[w * 48 + (jj2 * 3 + 0) * 8 + bb];
      float sz = red[w * 48 + (jj2 * 3 + 1) * 8 + bb];
      float sn = red[w * 48 + (jj2 * 3 + 2) * 8 + bb];
      int rbase = rg * 6 + jj2 * 3;
      const float* xgp = g_xg + ((size_t)t * BATCH + b) * G3;
      float xr = xgp[j];
      float xz = xgp[HID + j];
      float xn = xgp[2 * HID + j];
      float rgate = sigmoid_f(xr + sr + bh[rbase + 0]);
      float zgate = sigmoid_f(xz + sz + bh[rbase + 1]);
      float hn_pre = sn + bh[rbase + 2];
      float ngate = tanh_f(xn + rgate * hn_pre);
      float hprev = hs[b * HID + j];
      float hnew = ngate + zgate * (hprev - ngate);
      hn[b * HID + j] = hnew;
      out[((size_t)b * SEQT + t) * HID + j] = hnew;
    }

    grid_barrier();  // h_t complete & visible before anyone stages step t+1
  }
}

// =============================================================
extern "C" void kernel_launch(void* const* d_in, const int* in_sizes, int n_in,
                              void* d_out, int out_size) {
  (void)in_sizes; (void)n_in; (void)out_size;
  const float* input = (const float*)d_in[0];  // [32, 2048, 512]
  const float* h0    = (const float*)d_in[1];  // [1, 32, 512]
  const float* wih   = (const float*)d_in[2];  // [1536, 512]
  const float* whh   = (const float*)d_in[3];  // [1536, 512]
  const float* bih   = (const float*)d_in[4];  // [1536]
  const float* bhh   = (const float*)d_in[5];  // [1536]
  float* out = (float*)d_out;                  // [32, 2048, 512]

  cudaFuncSetAttribute(gru_scan, cudaFuncAttributeMaxDynamicSharedMemorySize,
                       SMEM_FLOATS * (int)sizeof(float));

  dim3 gA(G3 / 128, (BATCH * SEQT) / 128);     // 12 x 512 blocks
  gemm_xgates<<<gA, 256>>>(input, wih, bih);
  gru_scan<<<NB, NT, SMEM_FLOATS * sizeof(float)>>>(whh, bhh, h0, out);
}